// round 2
// baseline (speedup 1.0000x reference)
#include <cuda_runtime.h>

#define B_  512
#define T_  1024
#define D_  128
#define H_  256
#define G_  1024   // 4*H
#define K1  384    // D + H
#define K2  512    // 2H
#define BM  32     // batch tile
#define BJ  32     // hidden tile
#define BN  128    // 4 * BJ gate columns
#define BK  64
#define NCTA 128   // 16 M-tiles * 8 J-tiles
#define NTHREADS 256

// Persistent state (double-buffered h, single-buffered c)
__device__ float g_h1[2][B_ * H_];
__device__ float g_c1[B_ * H_];
__device__ float g_h2[2][B_ * H_];
__device__ float g_c2[B_ * H_];

// Grid barrier state (sense-reversing; returns to {0,0} after an even barrier count)
__device__ unsigned g_bar_cnt = 0;
__device__ unsigned g_bar_sense = 0;

__device__ __forceinline__ void grid_barrier(unsigned& local_sense) {
    __syncthreads();
    if (threadIdx.x == 0) {
        unsigned want = local_sense ^ 1u;
        __threadfence();
        unsigned arrived = atomicAdd(&g_bar_cnt, 1u);
        if (arrived == NCTA - 1) {
            g_bar_cnt = 0;
            __threadfence();
            atomicExch(&g_bar_sense, want);
        } else {
            volatile unsigned* s = &g_bar_sense;
            while (*s != want) { __nanosleep(64); }
            __threadfence();
        }
        local_sense = want;
    }
    __syncthreads();
}

__device__ __forceinline__ float fsig(float x)  { return 1.0f / (1.0f + __expf(-x)); }
__device__ __forceinline__ float ftanh(float x) { return 2.0f / (1.0f + __expf(-2.0f * x)) - 1.0f; }

// One LSTM layer step for this CTA's (batch-tile, hidden-tile).
// A[b][k] = (k < SPLIT) ? src0[b*stride0 + k] : src1[b*H + k - SPLIT]
// gates = A @ W + bias, columns {g*H + j0 + jj : g in 0..3, jj in 0..31}
template<int K, int SPLIT>
__device__ void lstm_phase(const float* __restrict__ src0, int stride0,
                           const float* __restrict__ src1,
                           const float* __restrict__ W,
                           const float* __restrict__ bias,
                           float* __restrict__ hout,
                           float* __restrict__ cst,
                           int bm0, int j0,
                           float* __restrict__ Ws,   // BK*BN floats (reused as gate staging)
                           float* __restrict__ As)   // BM*BK floats
{
    const int tid = threadIdx.x;
    const int tx  = tid & 31;   // 0..31 -> 4 gate columns each
    const int ty  = tid >> 5;   // 0..7  -> 4 batch rows each

    float acc[4][4] = {};

    for (int k0 = 0; k0 < K; k0 += BK) {
        // ---- load A tile: BM x BK (k-fast -> coalesced global, conflict-free STS)
        #pragma unroll
        for (int p = 0; p < (BM * BK) / NTHREADS; ++p) {   // 8
            int e = p * NTHREADS + tid;
            int m = e >> 6;       // / BK
            int k = e & (BK - 1);
            int kg = k0 + k;
            int b = bm0 + m;
            float v = (kg < SPLIT) ? src0[b * stride0 + kg]
                                   : src1[b * H_ + (kg - SPLIT)];
            As[m * BK + k] = v;
        }
        // ---- load W tile: BK rows x 128 cols (4 segments of 32 per row)
        #pragma unroll
        for (int p = 0; p < BK / 8; ++p) {                 // 8 passes, 8 rows each
            int krow = p * 8 + (tid >> 5);
            int ln4  = (tid & 31) * 4;
            int g    = ln4 >> 5;
            int jj   = ln4 & 31;
            const float4 wv = *(const float4*)&W[(size_t)(k0 + krow) * G_ + g * H_ + j0 + jj];
            *(float4*)&Ws[krow * BN + ln4] = wv;
        }
        __syncthreads();

        // ---- FMA mainloop
        #pragma unroll 16
        for (int kk = 0; kk < BK; ++kk) {
            float a0 = As[(ty * 4 + 0) * BK + kk];
            float a1 = As[(ty * 4 + 1) * BK + kk];
            float a2 = As[(ty * 4 + 2) * BK + kk];
            float a3 = As[(ty * 4 + 3) * BK + kk];
            float4 bv = *(float4*)&Ws[kk * BN + tx * 4];
            acc[0][0] += a0 * bv.x; acc[0][1] += a0 * bv.y; acc[0][2] += a0 * bv.z; acc[0][3] += a0 * bv.w;
            acc[1][0] += a1 * bv.x; acc[1][1] += a1 * bv.y; acc[1][2] += a1 * bv.z; acc[1][3] += a1 * bv.w;
            acc[2][0] += a2 * bv.x; acc[2][1] += a2 * bv.y; acc[2][2] += a2 * bv.z; acc[2][3] += a2 * bv.w;
            acc[3][0] += a3 * bv.x; acc[3][1] += a3 * bv.y; acc[3][2] += a3 * bv.z; acc[3][3] += a3 * bv.w;
        }
        __syncthreads();
    }

    // ---- stage gates (reuse Ws): layout [m][ln], ln = gate*32 + jj
    #pragma unroll
    for (int i = 0; i < 4; ++i)
        #pragma unroll
        for (int j = 0; j < 4; ++j)
            Ws[(ty * 4 + i) * BN + (tx * 4 + j)] = acc[i][j];
    __syncthreads();

    // ---- cell update: 32 m x 32 jj pairs, 4 per thread
    #pragma unroll
    for (int p = 0; p < (BM * BJ) / NTHREADS; ++p) {       // 4
        int e  = p * NTHREADS + tid;
        int m  = e >> 5;
        int jj = e & 31;
        float gf = Ws[m * BN + 0 * 32 + jj] + bias[0 * H_ + j0 + jj];
        float gi = Ws[m * BN + 1 * 32 + jj] + bias[1 * H_ + j0 + jj];
        float gg = Ws[m * BN + 2 * 32 + jj] + bias[2 * H_ + j0 + jj];
        float go = Ws[m * BN + 3 * 32 + jj] + bias[3 * H_ + j0 + jj];
        float f  = fsig(gf);
        float ii = fsig(gi);
        float g  = ftanh(gg);
        float o  = fsig(go);
        int idx  = (bm0 + m) * H_ + j0 + jj;
        float c  = f * cst[idx] + ii * g;
        cst[idx]  = c;
        hout[idx] = o * ftanh(c);
    }
    __syncthreads();   // protect Ws before next phase reuses it
}

__global__ void __launch_bounds__(NTHREADS, 1)
lstm_persistent_kernel(const float* __restrict__ x,
                       const float* __restrict__ W1, const float* __restrict__ b1,
                       const float* __restrict__ W2, const float* __restrict__ b2,
                       const float* __restrict__ Wout, const float* __restrict__ bout,
                       float* __restrict__ out)
{
    __shared__ float Ws[BK * BN];   // 32 KB
    __shared__ float As[BM * BK];   // 8 KB

    unsigned sense = 0;
    const int cta = blockIdx.x;
    const int bm0 = (cta >> 3) * BM;   // 16 batch tiles
    const int j0  = (cta & 7) * BJ;    // 8 hidden tiles

    // ---- zero all state
    {
        int gtid = cta * NTHREADS + threadIdx.x;
        int nthr = NCTA * NTHREADS;
        for (int i = gtid; i < B_ * H_; i += nthr) {
            g_h1[0][i] = 0.f; g_h1[1][i] = 0.f; g_c1[i] = 0.f;
            g_h2[0][i] = 0.f; g_h2[1][i] = 0.f; g_c2[i] = 0.f;
        }
    }
    grid_barrier(sense);               // barrier #1

    int p = 0, q = 0;
    for (int t = 0; t < T_; ++t) {
        // Layer 1: A = [x_t, h1(prev)], writes h1(cur) into other buffer
        lstm_phase<K1, D_>(x + (size_t)t * D_, T_ * D_, g_h1[p],
                           W1, b1, g_h1[p ^ 1], g_c1, bm0, j0, Ws, As);
        grid_barrier(sense);
        // Layer 2: A = [h1(cur), h2(prev)]
        lstm_phase<K2, H_>(g_h1[p ^ 1], H_, g_h2[q],
                           W2, b2, g_h2[q ^ 1], g_c2, bm0, j0, Ws, As);
        grid_barrier(sense);
        p ^= 1; q ^= 1;
    }
    // 1 + 2048 barriers so far; g_h2[q] holds the final h2.

    // ---- output projection: out[b] = h2_final[b] . Wout + bout
    {
        const float* h2f = g_h2[q];
        int gtid = cta * NTHREADS + threadIdx.x;
        if (gtid < B_) {
            float s = 0.f;
            #pragma unroll 8
            for (int k = 0; k < H_; ++k)
                s += h2f[gtid * H_ + k] * Wout[k];
            out[gtid] = s + bout[0];
        }
    }
    grid_barrier(sense);               // barrier #2050 (even -> state resets for replay)
}

extern "C" void kernel_launch(void* const* d_in, const int* in_sizes, int n_in,
                              void* d_out, int out_size)
{
    (void)in_sizes; (void)n_in; (void)out_size;
    const float* x    = (const float*)d_in[0];
    const float* W1   = (const float*)d_in[1];
    const float* b1   = (const float*)d_in[2];
    const float* W2   = (const float*)d_in[3];
    const float* b2   = (const float*)d_in[4];
    const float* Wout = (const float*)d_in[5];
    const float* bout = (const float*)d_in[6];
    lstm_persistent_kernel<<<NCTA, NTHREADS>>>(x, W1, b1, W2, b2, Wout, bout,
                                               (float*)d_out);
}

// round 3
// speedup vs baseline: 1.0014x; 1.0014x over previous
#include <cuda_runtime.h>

#define B_  512
#define T_  1024
#define D_  128
#define H_  256
#define G_  1024   // 4*H
#define K1  384    // D + H
#define K2  512    // 2H
#define BM  32     // batch tile
#define BJ  32     // hidden tile
#define BN  128    // 4 * BJ gate columns
#define BK  64
#define NCTA 128   // 16 M-tiles * 8 J-tiles
#define NTHREADS 256

// Persistent state (double-buffered h, single-buffered c)
__device__ float g_h1[2][B_ * H_];
__device__ float g_c1[B_ * H_];
__device__ float g_h2[2][B_ * H_];
__device__ float g_c2[B_ * H_];

// Grid barrier state (sense-reversing; returns to {0,0} after an even barrier count)
__device__ unsigned g_bar_cnt = 0;
__device__ unsigned g_bar_sense = 0;

__device__ __forceinline__ void grid_barrier(unsigned& local_sense) {
    __syncthreads();
    if (threadIdx.x == 0) {
        unsigned want = local_sense ^ 1u;
        __threadfence();
        unsigned arrived = atomicAdd(&g_bar_cnt, 1u);
        if (arrived == NCTA - 1) {
            g_bar_cnt = 0;
            __threadfence();
            atomicExch(&g_bar_sense, want);
        } else {
            volatile unsigned* s = &g_bar_sense;
            while (*s != want) { __nanosleep(64); }
            __threadfence();
        }
        local_sense = want;
    }
    __syncthreads();
}

__device__ __forceinline__ float fsig(float x)  { return 1.0f / (1.0f + __expf(-x)); }
__device__ __forceinline__ float ftanh(float x) { return 2.0f / (1.0f + __expf(-2.0f * x)) - 1.0f; }

// One LSTM layer step for this CTA's (batch-tile, hidden-tile).
// A[b][k] = (k < SPLIT) ? src0[b*stride0 + k] : src1[b*H + k - SPLIT]
// gates = A @ W + bias, columns {g*H + j0 + jj : g in 0..3, jj in 0..31}
template<int K, int SPLIT>
__device__ void lstm_phase(const float* __restrict__ src0, int stride0,
                           const float* __restrict__ src1,
                           const float* __restrict__ W,
                           const float* __restrict__ bias,
                           float* __restrict__ hout,
                           float* __restrict__ cst,
                           int bm0, int j0,
                           float* __restrict__ Ws,   // BK*BN floats (reused as gate staging)
                           float* __restrict__ As)   // BM*BK floats
{
    const int tid = threadIdx.x;
    const int tx  = tid & 31;   // 0..31 -> 4 gate columns each
    const int ty  = tid >> 5;   // 0..7  -> 4 batch rows each

    float acc[4][4] = {};

    for (int k0 = 0; k0 < K; k0 += BK) {
        // ---- load A tile: BM x BK (k-fast -> coalesced global, conflict-free STS)
        #pragma unroll
        for (int p = 0; p < (BM * BK) / NTHREADS; ++p) {   // 8
            int e = p * NTHREADS + tid;
            int m = e >> 6;       // / BK
            int k = e & (BK - 1);
            int kg = k0 + k;
            int b = bm0 + m;
            float v = (kg < SPLIT) ? src0[b * stride0 + kg]
                                   : src1[b * H_ + (kg - SPLIT)];
            As[m * BK + k] = v;
        }
        // ---- load W tile: BK rows x 128 cols (4 segments of 32 per row)
        #pragma unroll
        for (int p = 0; p < BK / 8; ++p) {                 // 8 passes, 8 rows each
            int krow = p * 8 + (tid >> 5);
            int ln4  = (tid & 31) * 4;
            int g    = ln4 >> 5;
            int jj   = ln4 & 31;
            const float4 wv = *(const float4*)&W[(size_t)(k0 + krow) * G_ + g * H_ + j0 + jj];
            *(float4*)&Ws[krow * BN + ln4] = wv;
        }
        __syncthreads();

        // ---- FMA mainloop
        #pragma unroll 16
        for (int kk = 0; kk < BK; ++kk) {
            float a0 = As[(ty * 4 + 0) * BK + kk];
            float a1 = As[(ty * 4 + 1) * BK + kk];
            float a2 = As[(ty * 4 + 2) * BK + kk];
            float a3 = As[(ty * 4 + 3) * BK + kk];
            float4 bv = *(float4*)&Ws[kk * BN + tx * 4];
            acc[0][0] += a0 * bv.x; acc[0][1] += a0 * bv.y; acc[0][2] += a0 * bv.z; acc[0][3] += a0 * bv.w;
            acc[1][0] += a1 * bv.x; acc[1][1] += a1 * bv.y; acc[1][2] += a1 * bv.z; acc[1][3] += a1 * bv.w;
            acc[2][0] += a2 * bv.x; acc[2][1] += a2 * bv.y; acc[2][2] += a2 * bv.z; acc[2][3] += a2 * bv.w;
            acc[3][0] += a3 * bv.x; acc[3][1] += a3 * bv.y; acc[3][2] += a3 * bv.z; acc[3][3] += a3 * bv.w;
        }
        __syncthreads();
    }

    // ---- stage gates (reuse Ws): layout [m][ln], ln = gate*32 + jj
    #pragma unroll
    for (int i = 0; i < 4; ++i)
        #pragma unroll
        for (int j = 0; j < 4; ++j)
            Ws[(ty * 4 + i) * BN + (tx * 4 + j)] = acc[i][j];
    __syncthreads();

    // ---- cell update: 32 m x 32 jj pairs, 4 per thread
    #pragma unroll
    for (int p = 0; p < (BM * BJ) / NTHREADS; ++p) {       // 4
        int e  = p * NTHREADS + tid;
        int m  = e >> 5;
        int jj = e & 31;
        float gf = Ws[m * BN + 0 * 32 + jj] + bias[0 * H_ + j0 + jj];
        float gi = Ws[m * BN + 1 * 32 + jj] + bias[1 * H_ + j0 + jj];
        float gg = Ws[m * BN + 2 * 32 + jj] + bias[2 * H_ + j0 + jj];
        float go = Ws[m * BN + 3 * 32 + jj] + bias[3 * H_ + j0 + jj];
        float f  = fsig(gf);
        float ii = fsig(gi);
        float g  = ftanh(gg);
        float o  = fsig(go);
        int idx  = (bm0 + m) * H_ + j0 + jj;
        float c  = f * cst[idx] + ii * g;
        cst[idx]  = c;
        hout[idx] = o * ftanh(c);
    }
    __syncthreads();   // protect Ws before next phase reuses it
}

__global__ void __launch_bounds__(NTHREADS, 1)
lstm_persistent_kernel(const float* __restrict__ x,
                       const float* __restrict__ W1, const float* __restrict__ b1,
                       const float* __restrict__ W2, const float* __restrict__ b2,
                       const float* __restrict__ Wout, const float* __restrict__ bout,
                       float* __restrict__ out)
{
    __shared__ float Ws[BK * BN];   // 32 KB
    __shared__ float As[BM * BK];   // 8 KB

    unsigned sense = 0;
    const int cta = blockIdx.x;
    const int bm0 = (cta >> 3) * BM;   // 16 batch tiles
    const int j0  = (cta & 7) * BJ;    // 8 hidden tiles

    // ---- zero all state
    {
        int gtid = cta * NTHREADS + threadIdx.x;
        int nthr = NCTA * NTHREADS;
        for (int i = gtid; i < B_ * H_; i += nthr) {
            g_h1[0][i] = 0.f; g_h1[1][i] = 0.f; g_c1[i] = 0.f;
            g_h2[0][i] = 0.f; g_h2[1][i] = 0.f; g_c2[i] = 0.f;
        }
    }
    grid_barrier(sense);               // barrier #1

    int p = 0, q = 0;
    for (int t = 0; t < T_; ++t) {
        // Layer 1: A = [x_t, h1(prev)], writes h1(cur) into other buffer
        lstm_phase<K1, D_>(x + (size_t)t * D_, T_ * D_, g_h1[p],
                           W1, b1, g_h1[p ^ 1], g_c1, bm0, j0, Ws, As);
        grid_barrier(sense);
        // Layer 2: A = [h1(cur), h2(prev)]
        lstm_phase<K2, H_>(g_h1[p ^ 1], H_, g_h2[q],
                           W2, b2, g_h2[q ^ 1], g_c2, bm0, j0, Ws, As);
        grid_barrier(sense);
        p ^= 1; q ^= 1;
    }
    // 1 + 2048 barriers so far; g_h2[q] holds the final h2.

    // ---- output projection: out[b] = h2_final[b] . Wout + bout
    {
        const float* h2f = g_h2[q];
        int gtid = cta * NTHREADS + threadIdx.x;
        if (gtid < B_) {
            float s = 0.f;
            #pragma unroll 8
            for (int k = 0; k < H_; ++k)
                s += h2f[gtid * H_ + k] * Wout[k];
            out[gtid] = s + bout[0];
        }
    }
    grid_barrier(sense);               // barrier #2050 (even -> state resets for replay)
}

extern "C" void kernel_launch(void* const* d_in, const int* in_sizes, int n_in,
                              void* d_out, int out_size)
{
    (void)in_sizes; (void)n_in; (void)out_size;
    const float* x    = (const float*)d_in[0];
    const float* W1   = (const float*)d_in[1];
    const float* b1   = (const float*)d_in[2];
    const float* W2   = (const float*)d_in[3];
    const float* b2   = (const float*)d_in[4];
    const float* Wout = (const float*)d_in[5];
    const float* bout = (const float*)d_in[6];
    lstm_persistent_kernel<<<NCTA, NTHREADS>>>(x, W1, b1, W2, b2, Wout, bout,
                                               (float*)d_out);
}

// round 5
// speedup vs baseline: 2.5911x; 2.5875x over previous
#include <cuda_runtime.h>
#include <cuda_bf16.h>
#include <cstdint>

#define B_   512
#define T_   1024
#define H_   256
#define NCTA 128
#define NTH  128
#define STG  32768
#define SMEM_DYN (1024 + 3*STG + 18432)

__device__ uint4 g_x_hi[8388608], g_x_lo[8388608];   // [t][512][128] bf16 as 16B granules
__device__ uint4 g_w1_hi[49152],  g_w1_lo[49152];    // [n'=1024][384]
__device__ uint4 g_w2_hi[65536],  g_w2_lo[65536];    // [n'=1024][512]
__device__ uint4 g_h1_hi[32768],  g_h1_lo[32768];    // [buf2][512][256]
__device__ uint4 g_h2_hi[32768],  g_h2_lo[32768];
__device__ float g_h2f[B_ * H_];
__device__ unsigned g_bar_cnt = 0, g_bar_sense = 0;

__device__ __forceinline__ uint32_t sm32(const void* p) {
    uint32_t a;
    asm("{ .reg .u64 t; cvta.to.shared.u64 t, %1; cvt.u32.u64 %0, t; }" : "=r"(a) : "l"(p));
    return a;
}
__device__ __forceinline__ void cp16(uint32_t d, const void* s) {
    asm volatile("cp.async.cg.shared.global [%0], [%1], 16;" :: "r"(d), "l"(s));
}
__device__ __forceinline__ void cp_commit() { asm volatile("cp.async.commit_group;" ::: "memory"); }
template<int N> __device__ __forceinline__ void cp_wait() {
    asm volatile("cp.async.wait_group %0;" :: "n"(N) : "memory");
}
__device__ __forceinline__ void ldsm4(uint32_t& r0, uint32_t& r1, uint32_t& r2, uint32_t& r3, uint32_t a) {
    asm volatile("ldmatrix.sync.aligned.m8n8.x4.shared.b16 {%0,%1,%2,%3}, [%4];"
        : "=r"(r0), "=r"(r1), "=r"(r2), "=r"(r3) : "r"(a));
}
__device__ __forceinline__ void mma16816(float* d, const uint32_t* a, const uint32_t* b) {
    asm volatile("mma.sync.aligned.m16n8k16.row.col.f32.bf16.bf16.f32 "
        "{%0,%1,%2,%3}, {%4,%5,%6,%7}, {%8,%9}, {%0,%1,%2,%3};"
        : "+f"(d[0]), "+f"(d[1]), "+f"(d[2]), "+f"(d[3])
        : "r"(a[0]), "r"(a[1]), "r"(a[2]), "r"(a[3]), "r"(b[0]), "r"(b[1]));
}
__device__ __forceinline__ float fsig(float x)  { return 1.0f / (1.0f + __expf(-x)); }
__device__ __forceinline__ float ftanh(float x) { return 2.0f / (1.0f + __expf(-2.0f * x)) - 1.0f; }

__device__ __forceinline__ void grid_barrier() {
    __threadfence();
    __syncthreads();
    __shared__ unsigned want_s;
    if (threadIdx.x == 0) {
        unsigned want = g_bar_sense ^ 0;  // read not needed; use counter-derived sense
        (void)want;
    }
    // sense-reversing: each CTA tracks via static? use simple two-counter scheme below
    __syncthreads();
}

// proper sense-reversing barrier with caller-held sense
__device__ __forceinline__ void gbar(unsigned& sense) {
    unsigned want = sense ^ 1u;
    __threadfence();
    __syncthreads();
    if (threadIdx.x == 0) {
        if (atomicAdd(&g_bar_cnt, 1u) == NCTA - 1) {
            g_bar_cnt = 0; __threadfence(); atomicExch(&g_bar_sense, want);
        } else {
            while (*(volatile unsigned*)&g_bar_sense != want) __nanosleep(32);
            __threadfence();
        }
    }
    __syncthreads();
    sense = want;
}

__device__ __forceinline__ void split8(const float* v, uint4& uh, uint4& ul) {
    uint32_t ph[4], pl[4];
    #pragma unroll
    for (int e = 0; e < 4; ++e) {
        __nv_bfloat16 b0 = __float2bfloat16(v[2*e]),   b1 = __float2bfloat16(v[2*e+1]);
        __nv_bfloat16 l0 = __float2bfloat16(v[2*e]   - __bfloat162float(b0));
        __nv_bfloat16 l1 = __float2bfloat16(v[2*e+1] - __bfloat162float(b1));
        ph[e] = (uint32_t)__bfloat16_as_ushort(b0) | ((uint32_t)__bfloat16_as_ushort(b1) << 16);
        pl[e] = (uint32_t)__bfloat16_as_ushort(l0) | ((uint32_t)__bfloat16_as_ushort(l1) << 16);
    }
    uh = make_uint4(ph[0], ph[1], ph[2], ph[3]);
    ul = make_uint4(pl[0], pl[1], pl[2], pl[3]);
}

// copy one 64x64 A tile (hi+lo) + 64x64 W tile (hi+lo) into stage sb, swizzled
__device__ __forceinline__ void copy_chunk(uint32_t sb, int tid,
    const uint4* ah, const uint4* al, int astr,
    const uint4* wh, const uint4* wl, int wstr)
{
    #pragma unroll
    for (int i = 0; i < 4; ++i) {
        int idx = i * 128 + tid;
        int r = idx >> 3, g = idx & 7;
        uint32_t d = sb + (uint32_t)r * 128 + (uint32_t)((g ^ (r & 7)) << 4);
        cp16(d,         ah + (size_t)r * astr + g);
        cp16(d + 8192,  al + (size_t)r * astr + g);
        cp16(d + 16384, wh + (size_t)r * wstr + g);
        cp16(d + 24576, wl + (size_t)r * wstr + g);
    }
    cp_commit();
}

// consume one stage: 4 k-blocks, bf16x3 emulated mma
__device__ __forceinline__ void compute_chunk(uint32_t sb, int lane, int wr, int wc,
                                              float (&acc)[2][4][4])
{
    const int t_ = lane >> 3, l7 = lane & 7;
    #pragma unroll
    for (int kb = 0; kb < 4; ++kb) {
        uint32_t ah[2][4], al[2][4], bh[8], bl[8];
        #pragma unroll
        for (int mb = 0; mb < 2; ++mb) {
            int trow = wr + mb * 16 + ((t_ & 1) << 3) + l7;
            int tg = kb * 2 + (t_ >> 1);
            uint32_t ad = sb + (uint32_t)trow * 128 + (uint32_t)((tg ^ (trow & 7)) << 4);
            ldsm4(ah[mb][0], ah[mb][1], ah[mb][2], ah[mb][3], ad);
            ldsm4(al[mb][0], al[mb][1], al[mb][2], al[mb][3], ad + 8192);
        }
        #pragma unroll
        for (int np = 0; np < 2; ++np) {
            int trow = wc + np * 16 + ((t_ >> 1) << 3) + l7;
            int tg = kb * 2 + (t_ & 1);
            uint32_t bd = sb + 16384 + (uint32_t)trow * 128 + (uint32_t)((tg ^ (trow & 7)) << 4);
            ldsm4(bh[np*4+0], bh[np*4+1], bh[np*4+2], bh[np*4+3], bd);
            ldsm4(bl[np*4+0], bl[np*4+1], bl[np*4+2], bl[np*4+3], bd + 8192);
        }
        #pragma unroll
        for (int mb = 0; mb < 2; ++mb)
            #pragma unroll
            for (int nb = 0; nb < 4; ++nb) {
                const uint32_t* bhp = &bh[(nb >> 1) * 4 + (nb & 1) * 2];
                const uint32_t* blp = &bl[(nb >> 1) * 4 + (nb & 1) * 2];
                mma16816(acc[mb][nb], ah[mb], bhp);
                mma16816(acc[mb][nb], ah[mb], blp);
                mma16816(acc[mb][nb], al[mb], bhp);
            }
    }
}

// chunk source select: chunks [0,N0) from a0 (stride S0), rest from a1 (stride S1)
#define SRC(c) \
    const uint4* sah = ((c) < N0) ? a0h + (c)*8 : a1h + ((c)-N0)*8; \
    const uint4* sal = ((c) < N0) ? a0l + (c)*8 : a1l + ((c)-N0)*8; \
    int sstr = ((c) < N0) ? S0 : S1;

template<int NC, int N0, int S0, int S1>
__device__ __forceinline__ void gemm_prol(uint32_t base32, int tid,
    const uint4* a0h, const uint4* a0l, const uint4* a1h, const uint4* a1l,
    const uint4* wh, const uint4* wl, int wstr)
{
    #pragma unroll
    for (int c = 0; c < 3; ++c) {
        SRC(c);
        copy_chunk(base32 + c * STG, tid, sah, sal, sstr, wh + c * 8, wl + c * 8, wstr);
    }
}

template<int NC, int N0, int S0, int S1>
__device__ __forceinline__ void gemm_main(uint32_t base32, int tid, int lane, int wr, int wc,
    const uint4* a0h, const uint4* a0l, const uint4* a1h, const uint4* a1l,
    const uint4* wh, const uint4* wl, int wstr, float (&acc)[2][4][4])
{
    #pragma unroll
    for (int c = 0; c < NC; ++c) {
        if (c < NC - 2) cp_wait<2>(); else if (c == NC - 2) cp_wait<1>(); else cp_wait<0>();
        __syncthreads();
        compute_chunk(base32 + (c % 3) * STG, lane, wr, wc, acc);
        __syncthreads();
        if (c + 3 < NC) {
            SRC(c + 3);
            copy_chunk(base32 + ((c + 3) % 3) * STG, tid, sah, sal, sstr,
                       wh + (c + 3) * 8, wl + (c + 3) * 8, wstr);
        }
    }
}

__device__ __forceinline__ void epilogue(float (&acc)[2][4][4], float* sG, const float* sb,
    float (&cst)[8], uint4* dhi, uint4* dlo, float* h2fb,
    int tid, int lane, int warp)
{
    int wr = (warp >> 1) * 32, wc = (warp & 1) * 32;
    #pragma unroll
    for (int mb = 0; mb < 2; ++mb)
        #pragma unroll
        for (int nb = 0; nb < 4; ++nb) {
            int r0 = wr + mb * 16 + (lane >> 2);
            int cc = wc + nb * 8 + (lane & 3) * 2;
            *(float2*)&sG[r0 * 72 + cc]       = make_float2(acc[mb][nb][0], acc[mb][nb][1]);
            *(float2*)&sG[(r0 + 8) * 72 + cc] = make_float2(acc[mb][nb][2], acc[mb][nb][3]);
        }
    __syncthreads();
    int r = tid >> 1, jq = (tid & 1) * 8;
    float hv[8];
    #pragma unroll
    for (int u = 0; u < 8; ++u) {
        int jj = jq + u;
        float f = fsig (sG[r * 72 + jj]      + sb[jj]);
        float i = fsig (sG[r * 72 + 16 + jj] + sb[16 + jj]);
        float g = ftanh(sG[r * 72 + 32 + jj] + sb[32 + jj]);
        float o = fsig (sG[r * 72 + 48 + jj] + sb[48 + jj]);
        float c = f * cst[u] + i * g;
        cst[u] = c;
        hv[u] = o * ftanh(c);
    }
    uint4 uh, ul;
    split8(hv, uh, ul);
    dhi[(size_t)r * 32 + (tid & 1)] = uh;
    dlo[(size_t)r * 32 + (tid & 1)] = ul;
    if (h2fb) {
        #pragma unroll
        for (int u = 0; u < 8; ++u) h2fb[(size_t)r * 256 + jq + u] = hv[u];
    }
    __syncthreads();
}

__global__ void __launch_bounds__(NTH, 1)
lstm_mma_kernel(const float* __restrict__ b1, const float* __restrict__ b2,
                const float* __restrict__ Wout, const float* __restrict__ bout,
                float* __restrict__ out)
{
    extern __shared__ uint4 dsm[];
    __shared__ float s_b1[64], s_b2[64];

    const int tid = threadIdx.x, cta = blockIdx.x;
    const int warp = tid >> 5, lane = tid & 31;
    const int mt = cta >> 4, jt = cta & 15;
    const int wr = (warp >> 1) * 32, wc = (warp & 1) * 32;
    uint32_t base32 = (sm32(dsm) + 1023u) & ~1023u;
    float* sG = (float*)((char*)dsm + ((base32 - sm32(dsm)) + 3 * STG));

    if (tid < 64) {
        s_b1[tid] = b1[(tid >> 4) * H_ + jt * 16 + (tid & 15)];
        s_b2[tid] = b2[(tid >> 4) * H_ + jt * 16 + (tid & 15)];
    }
    {   // zero h planes
        uint4 z = make_uint4(0, 0, 0, 0);
        for (int i = cta * NTH + tid; i < 32768; i += NCTA * NTH) {
            g_h1_hi[i] = z; g_h1_lo[i] = z; g_h2_hi[i] = z; g_h2_lo[i] = z;
        }
    }
    unsigned sense = 0;
    gbar(sense);                                   // barrier #1

    float c1[8], c2[8];
    #pragma unroll
    for (int u = 0; u < 8; ++u) { c1[u] = 0.f; c2[u] = 0.f; }

    const uint4* w1h = g_w1_hi + (size_t)(jt * 64) * 48;
    const uint4* w1l = g_w1_lo + (size_t)(jt * 64) * 48;
    const uint4* w2h = g_w2_hi + (size_t)(jt * 64) * 64;
    const uint4* w2l = g_w2_lo + (size_t)(jt * 64) * 64;

    for (int p = 0; p < 1025; ++p) {
        const bool do1 = p < 1024, do2 = p > 0;
        float acc1[2][4][4], acc2[2][4][4];

        // ---- layer-2 source pointers (t2 = p-1) ----
        const int rb1 = (p - 1) & 1;               // h1(t2) buffer
        const int rb2 = p & 1;                     // h2(t2-1) buffer
        const uint4* h1r_h = g_h1_hi + ((size_t)rb1 * 512 + mt * 64) * 32;
        const uint4* h1r_l = g_h1_lo + ((size_t)rb1 * 512 + mt * 64) * 32;
        const uint4* h2r_h = g_h2_hi + ((size_t)rb2 * 512 + mt * 64) * 32;
        const uint4* h2r_l = g_h2_lo + ((size_t)rb2 * 512 + mt * 64) * 32;

        if (do1) {
            // layer 1, t1 = p: A = [x_t | h1(p-1)]
            const uint4* xh = g_x_hi + ((size_t)p * 512 + mt * 64) * 16;
            const uint4* xl = g_x_lo + ((size_t)p * 512 + mt * 64) * 16;
            #pragma unroll
            for (int mb = 0; mb < 2; ++mb)
                #pragma unroll
                for (int nb = 0; nb < 4; ++nb)
                    #pragma unroll
                    for (int e = 0; e < 4; ++e) acc1[mb][nb][e] = 0.f;
            gemm_prol<6,2,16,32>(base32, tid, xh, xl, h1r_h, h1r_l, w1h, w1l, 48);
            gemm_main<6,2,16,32>(base32, tid, lane, wr, wc, xh, xl, h1r_h, h1r_l,
                                 w1h, w1l, 48, acc1);
        }
        if (do2) {
            #pragma unroll
            for (int mb = 0; mb < 2; ++mb)
                #pragma unroll
                for (int nb = 0; nb < 4; ++nb)
                    #pragma unroll
                    for (int e = 0; e < 4; ++e) acc2[mb][nb][e] = 0.f;
            gemm_prol<8,4,32,32>(base32, tid, h1r_h, h1r_l, h2r_h, h2r_l, w2h, w2l, 64);
        }
        if (do1) {
            const int wb = p & 1;                  // h1(p) write buffer
            uint4* dh = g_h1_hi + ((size_t)wb * 512 + mt * 64) * 32 + jt * 2;
            uint4* dl = g_h1_lo + ((size_t)wb * 512 + mt * 64) * 32 + jt * 2;
            epilogue(acc1, sG, s_b1, c1, dh, dl, (float*)0, tid, lane, warp);
        }
        if (do2) {
            gemm_main<8,4,32,32>(base32, tid, lane, wr, wc, h1r_h, h1r_l, h2r_h, h2r_l,
                                 w2h, w2l, 64, acc2);
            const int wb = (p - 1) & 1;            // h2(p-1) write buffer
            uint4* dh = g_h2_hi + ((size_t)wb * 512 + mt * 64) * 32 + jt * 2;
            uint4* dl = g_h2_lo + ((size_t)wb * 512 + mt * 64) * 32 + jt * 2;
            float* hb = (p == 1024) ? g_h2f + (size_t)(mt * 64) * 256 + jt * 16 : (float*)0;
            epilogue(acc2, sG, s_b2, c2, dh, dl, hb, tid, lane, warp);
        }
        gbar(sense);                               // 1025 barriers -> total 1026 (even)
    }

    if (cta < 4) {
        int row = cta * 128 + tid;
        float s = 0.f;
        #pragma unroll 8
        for (int k = 0; k < H_; ++k) s += g_h2f[(size_t)row * H_ + k] * Wout[k];
        out[row] = s + bout[0];
    }
}

// ---------------- prep: split fp32 -> bf16 hi/lo planes ----------------
__global__ void prep_x_kernel(const float* __restrict__ x) {
    long gid = (long)blockIdx.x * 256 + threadIdx.x;       // 8,388,608
    int g = (int)(gid & 15);
    int b = (int)((gid >> 4) & 511);
    int t = (int)(gid >> 13);
    const float* src = x + ((size_t)b * 1024 + t) * 128 + g * 8;
    float4 f0 = *(const float4*)src, f1 = *(const float4*)(src + 4);
    float v[8] = {f0.x, f0.y, f0.z, f0.w, f1.x, f1.y, f1.z, f1.w};
    uint4 uh, ul;
    split8(v, uh, ul);
    size_t di = ((size_t)t * 512 + b) * 16 + g;
    g_x_hi[di] = uh; g_x_lo[di] = ul;
}

template<int K, int L>
__global__ void prep_w_kernel(const float* __restrict__ W) {
    uint4* dhi = (L == 1) ? g_w1_hi : g_w2_hi;
    uint4* dlo = (L == 1) ? g_w1_lo : g_w2_lo;
    int gid = blockIdx.x * 256 + threadIdx.x;              // 1024 * K/8
    int kg = gid % (K / 8);
    int np = gid / (K / 8);                                // n' = jt*64 + gate*16 + u
    int jt = np >> 6, gate = (np >> 4) & 3, u = np & 15;
    int col = gate * 256 + jt * 16 + u;
    float v[8];
    #pragma unroll
    for (int e = 0; e < 8; ++e) v[e] = W[(size_t)(kg * 8 + e) * 1024 + col];
    uint4 uh, ul;
    split8(v, uh, ul);
    dhi[(size_t)np * (K / 8) + kg] = uh;
    dlo[(size_t)np * (K / 8) + kg] = ul;
}

extern "C" void kernel_launch(void* const* d_in, const int* in_sizes, int n_in,
                              void* d_out, int out_size)
{
    (void)in_sizes; (void)n_in; (void)out_size;
    const float* x    = (const float*)d_in[0];
    const float* W1   = (const float*)d_in[1];
    const float* b1   = (const float*)d_in[2];
    const float* W2   = (const float*)d_in[3];
    const float* b2   = (const float*)d_in[4];
    const float* Wout = (const float*)d_in[5];
    const float* bout = (const float*)d_in[6];
    cudaFuncSetAttribute(lstm_mma_kernel, cudaFuncAttributeMaxDynamicSharedMemorySize, SMEM_DYN);
    prep_x_kernel<<<32768, 256>>>(x);
    prep_w_kernel<384, 1><<<192, 256>>>(W1);
    prep_w_kernel<512, 2><<<256, 256>>>(W2);
    lstm_mma_kernel<<<NCTA, NTH, SMEM_DYN>>>(b1, b2, Wout, bout, (float*)d_out);
}

// round 6
// speedup vs baseline: 3.0627x; 1.1820x over previous
#include <cuda_runtime.h>
#include <cuda_bf16.h>
#include <cstdint>

#define B_   512
#define T_   1024
#define H_   256
#define NCTA 128
#define NTH  256
#define STG  32768
#define SMEM_DYN (1024 + 3*STG + 18432)

__device__ uint4 g_x_hi[8388608], g_x_lo[8388608];   // [t][512][16 gran]
__device__ uint4 g_w1_hi[49152],  g_w1_lo[49152];    // [n'=1024][48 gran]
__device__ uint4 g_w2_hi[65536],  g_w2_lo[65536];    // [n'=1024][64 gran]
__device__ uint4 g_h1_hi[32768],  g_h1_lo[32768];    // [buf2][512][32 gran]
__device__ uint4 g_h2_hi[32768],  g_h2_lo[32768];
__device__ float g_h2f[B_ * H_];
__device__ unsigned g_bar_cnt = 0, g_bar_sense = 0;

__device__ __forceinline__ uint32_t sm32(const void* p) {
    uint32_t a;
    asm("{ .reg .u64 t; cvta.to.shared.u64 t, %1; cvt.u32.u64 %0, t; }" : "=r"(a) : "l"(p));
    return a;
}
__device__ __forceinline__ void cp16(uint32_t d, const void* s) {
    asm volatile("cp.async.cg.shared.global [%0], [%1], 16;" :: "r"(d), "l"(s));
}
__device__ __forceinline__ void cp_commit() { asm volatile("cp.async.commit_group;" ::: "memory"); }
template<int N> __device__ __forceinline__ void cp_wait() {
    asm volatile("cp.async.wait_group %0;" :: "n"(N) : "memory");
}
__device__ __forceinline__ void ldsm4(uint32_t& r0, uint32_t& r1, uint32_t& r2, uint32_t& r3, uint32_t a) {
    asm volatile("ldmatrix.sync.aligned.m8n8.x4.shared.b16 {%0,%1,%2,%3}, [%4];"
        : "=r"(r0), "=r"(r1), "=r"(r2), "=r"(r3) : "r"(a));
}
__device__ __forceinline__ void mma16816(float* d, const uint32_t* a, const uint32_t* b) {
    asm volatile("mma.sync.aligned.m16n8k16.row.col.f32.bf16.bf16.f32 "
        "{%0,%1,%2,%3}, {%4,%5,%6,%7}, {%8,%9}, {%0,%1,%2,%3};"
        : "+f"(d[0]), "+f"(d[1]), "+f"(d[2]), "+f"(d[3])
        : "r"(a[0]), "r"(a[1]), "r"(a[2]), "r"(a[3]), "r"(b[0]), "r"(b[1]));
}
__device__ __forceinline__ float fsig(float x)  { return 1.0f / (1.0f + __expf(-x)); }
__device__ __forceinline__ float ftanh(float x) { return 2.0f / (1.0f + __expf(-2.0f * x)) - 1.0f; }

__device__ __forceinline__ void gbar(unsigned& sense) {
    unsigned want = sense ^ 1u;
    __threadfence();
    __syncthreads();
    if (threadIdx.x == 0) {
        if (atomicAdd(&g_bar_cnt, 1u) == NCTA - 1) {
            g_bar_cnt = 0; __threadfence(); atomicExch(&g_bar_sense, want);
        } else {
            while (*(volatile unsigned*)&g_bar_sense != want) __nanosleep(32);
            __threadfence();
        }
    }
    __syncthreads();
    sense = want;
}

__device__ __forceinline__ void split8(const float* v, uint4& uh, uint4& ul) {
    uint32_t ph[4], pl[4];
    #pragma unroll
    for (int e = 0; e < 4; ++e) {
        __nv_bfloat16 b0 = __float2bfloat16(v[2*e]),   b1 = __float2bfloat16(v[2*e+1]);
        __nv_bfloat16 l0 = __float2bfloat16(v[2*e]   - __bfloat162float(b0));
        __nv_bfloat16 l1 = __float2bfloat16(v[2*e+1] - __bfloat162float(b1));
        ph[e] = (uint32_t)__bfloat16_as_ushort(b0) | ((uint32_t)__bfloat16_as_ushort(b1) << 16);
        pl[e] = (uint32_t)__bfloat16_as_ushort(l0) | ((uint32_t)__bfloat16_as_ushort(l1) << 16);
    }
    uh = make_uint4(ph[0], ph[1], ph[2], ph[3]);
    ul = make_uint4(pl[0], pl[1], pl[2], pl[3]);
}
__device__ __forceinline__ void split4(const float* v, uint2& uh, uint2& ul) {
    uint32_t ph[2], pl[2];
    #pragma unroll
    for (int e = 0; e < 2; ++e) {
        __nv_bfloat16 b0 = __float2bfloat16(v[2*e]),   b1 = __float2bfloat16(v[2*e+1]);
        __nv_bfloat16 l0 = __float2bfloat16(v[2*e]   - __bfloat162float(b0));
        __nv_bfloat16 l1 = __float2bfloat16(v[2*e+1] - __bfloat162float(b1));
        ph[e] = (uint32_t)__bfloat16_as_ushort(b0) | ((uint32_t)__bfloat16_as_ushort(b1) << 16);
        pl[e] = (uint32_t)__bfloat16_as_ushort(l0) | ((uint32_t)__bfloat16_as_ushort(l1) << 16);
    }
    uh = make_uint2(ph[0], ph[1]);
    ul = make_uint2(pl[0], pl[1]);
}

// copy one 64x64 A tile (hi+lo) + 64x64 W tile (hi+lo) into stage sb, swizzled
__device__ __forceinline__ void copy_chunk(uint32_t sb, int tid,
    const uint4* ah, const uint4* al, int astr,
    const uint4* wh, const uint4* wl, int wstr)
{
    #pragma unroll
    for (int i = 0; i < 2; ++i) {
        int idx = i * 256 + tid;
        int r = idx >> 3, g = idx & 7;
        uint32_t d = sb + (uint32_t)r * 128 + (uint32_t)((g ^ (r & 7)) << 4);
        cp16(d,         ah + (size_t)r * astr + g);
        cp16(d + 8192,  al + (size_t)r * astr + g);
        cp16(d + 16384, wh + (size_t)r * wstr + g);
        cp16(d + 24576, wl + (size_t)r * wstr + g);
    }
    cp_commit();
}

// consume one stage: warp tile 16 (rows) x 32 (cols), bf16x3 emulated mma
__device__ __forceinline__ void compute_chunk(uint32_t sb, int lane, int wr, int wc,
                                              float (&acc)[4][4])
{
    const int t_ = lane >> 3, l7 = lane & 7;
    #pragma unroll
    for (int kb = 0; kb < 4; ++kb) {
        uint32_t ah[4], al[4], bh[8], bl[8];
        {
            int trow = wr + ((t_ & 1) << 3) + l7;
            int tg = kb * 2 + (t_ >> 1);
            uint32_t ad = sb + (uint32_t)trow * 128 + (uint32_t)((tg ^ (trow & 7)) << 4);
            ldsm4(ah[0], ah[1], ah[2], ah[3], ad);
            ldsm4(al[0], al[1], al[2], al[3], ad + 8192);
        }
        #pragma unroll
        for (int np = 0; np < 2; ++np) {
            int trow = wc + np * 16 + ((t_ >> 1) << 3) + l7;
            int tg = kb * 2 + (t_ & 1);
            uint32_t bd = sb + 16384 + (uint32_t)trow * 128 + (uint32_t)((tg ^ (trow & 7)) << 4);
            ldsm4(bh[np*4+0], bh[np*4+1], bh[np*4+2], bh[np*4+3], bd);
            ldsm4(bl[np*4+0], bl[np*4+1], bl[np*4+2], bl[np*4+3], bd + 8192);
        }
        #pragma unroll
        for (int nb = 0; nb < 4; ++nb) {
            const uint32_t* bhp = &bh[(nb >> 1) * 4 + (nb & 1) * 2];
            const uint32_t* blp = &bl[(nb >> 1) * 4 + (nb & 1) * 2];
            mma16816(acc[nb], ah, bhp);
            mma16816(acc[nb], ah, blp);
            mma16816(acc[nb], al, bhp);
        }
    }
}

#define SRC(c) \
    const uint4* sah = ((c) < N0) ? a0h + (c)*8 : a1h + ((c)-N0)*8; \
    const uint4* sal = ((c) < N0) ? a0l + (c)*8 : a1l + ((c)-N0)*8; \
    int sstr = ((c) < N0) ? S0 : S1;

template<int NC, int N0, int S0, int S1>
__device__ __forceinline__ void gemm_prol(uint32_t base32, int tid,
    const uint4* a0h, const uint4* a0l, const uint4* a1h, const uint4* a1l,
    const uint4* wh, const uint4* wl, int wstr)
{
    #pragma unroll
    for (int c = 0; c < 3; ++c) {
        SRC(c);
        copy_chunk(base32 + c * STG, tid, sah, sal, sstr, wh + c * 8, wl + c * 8, wstr);
    }
}

template<int NC, int N0, int S0, int S1>
__device__ __forceinline__ void gemm_main(uint32_t base32, int tid, int lane, int wr, int wc,
    const uint4* a0h, const uint4* a0l, const uint4* a1h, const uint4* a1l,
    const uint4* wh, const uint4* wl, int wstr, float (&acc)[4][4])
{
    #pragma unroll
    for (int c = 0; c < NC; ++c) {
        if (c < NC - 2) cp_wait<2>(); else if (c == NC - 2) cp_wait<1>(); else cp_wait<0>();
        __syncthreads();
        compute_chunk(base32 + (c % 3) * STG, lane, wr, wc, acc);
        __syncthreads();
        if (c + 3 < NC) {
            SRC(c + 3);
            copy_chunk(base32 + ((c + 3) % 3) * STG, tid, sah, sal, sstr,
                       wh + (c + 3) * 8, wl + (c + 3) * 8, wstr);
        }
    }
}

// dhi/dlo: uint2* pre-offset to (buf,row0=mt*64,granule jt*2)
__device__ __forceinline__ void epilogue(float (&acc)[4][4], float* sG, const float* sb,
    float (&cst)[4], uint2* dhi, uint2* dlo, float* h2fb,
    int tid, int lane, int wr, int wc)
{
    #pragma unroll
    for (int nb = 0; nb < 4; ++nb) {
        int r0 = wr + (lane >> 2);
        int cc = wc + nb * 8 + (lane & 3) * 2;
        *(float2*)&sG[r0 * 72 + cc]       = make_float2(acc[nb][0], acc[nb][1]);
        *(float2*)&sG[(r0 + 8) * 72 + cc] = make_float2(acc[nb][2], acc[nb][3]);
    }
    __syncthreads();
    int r = tid >> 2, jq = (tid & 3) * 4;
    float hv[4];
    #pragma unroll
    for (int u = 0; u < 4; ++u) {
        int jj = jq + u;
        float f = fsig (sG[r * 72 + jj]      + sb[jj]);
        float i = fsig (sG[r * 72 + 16 + jj] + sb[16 + jj]);
        float g = ftanh(sG[r * 72 + 32 + jj] + sb[32 + jj]);
        float o = fsig (sG[r * 72 + 48 + jj] + sb[48 + jj]);
        float c = f * cst[u] + i * g;
        cst[u] = c;
        hv[u] = o * ftanh(c);
    }
    uint2 uh, ul;
    split4(hv, uh, ul);
    int di = r * 64 + (jq >> 3) * 2 + ((jq >> 2) & 1);
    dhi[di] = uh;
    dlo[di] = ul;
    if (h2fb) {
        #pragma unroll
        for (int u = 0; u < 4; ++u) h2fb[(size_t)r * 256 + jq + u] = hv[u];
    }
    __syncthreads();
}

__global__ void __launch_bounds__(NTH, 1)
lstm_mma_kernel(const float* __restrict__ b1, const float* __restrict__ b2,
                const float* __restrict__ Wout, const float* __restrict__ bout,
                float* __restrict__ out)
{
    extern __shared__ uint4 dsm[];
    __shared__ float s_b1[64], s_b2[64];

    const int tid = threadIdx.x, cta = blockIdx.x;
    const int warp = tid >> 5, lane = tid & 31;
    const int mt = cta >> 4, jt = cta & 15;
    const int wr = (warp & 3) * 16, wc = (warp >> 2) * 32;
    uint32_t base32 = (sm32(dsm) + 1023u) & ~1023u;
    float* sG = (float*)((char*)dsm + ((base32 - sm32(dsm)) + 3 * STG));

    if (tid < 64) {
        s_b1[tid] = b1[(tid >> 4) * H_ + jt * 16 + (tid & 15)];
        s_b2[tid] = b2[(tid >> 4) * H_ + jt * 16 + (tid & 15)];
    }
    {   // zero h planes
        uint4 z = make_uint4(0, 0, 0, 0);
        for (int i = cta * NTH + tid; i < 32768; i += NCTA * NTH) {
            g_h1_hi[i] = z; g_h1_lo[i] = z; g_h2_hi[i] = z; g_h2_lo[i] = z;
        }
    }
    unsigned sense = 0;
    gbar(sense);                                   // barrier #1

    float c1[4], c2[4];
    #pragma unroll
    for (int u = 0; u < 4; ++u) { c1[u] = 0.f; c2[u] = 0.f; }

    const uint4* w1h = g_w1_hi + (size_t)(jt * 64) * 48;
    const uint4* w1l = g_w1_lo + (size_t)(jt * 64) * 48;
    const uint4* w2h = g_w2_hi + (size_t)(jt * 64) * 64;
    const uint4* w2l = g_w2_lo + (size_t)(jt * 64) * 64;

    for (int p = 0; p < 1025; ++p) {
        const bool do1 = p < 1024, do2 = p > 0;
        float acc1[4][4], acc2[4][4];

        const int rb1 = (p - 1) & 1;               // h1(p-1) buffer
        const int rb2 = p & 1;                     // h2(p-2) buffer
        const uint4* h1r_h = g_h1_hi + ((size_t)rb1 * 512 + mt * 64) * 32;
        const uint4* h1r_l = g_h1_lo + ((size_t)rb1 * 512 + mt * 64) * 32;
        const uint4* h2r_h = g_h2_hi + ((size_t)rb2 * 512 + mt * 64) * 32;
        const uint4* h2r_l = g_h2_lo + ((size_t)rb2 * 512 + mt * 64) * 32;

        if (do1) {
            const uint4* xh = g_x_hi + ((size_t)p * 512 + mt * 64) * 16;
            const uint4* xl = g_x_lo + ((size_t)p * 512 + mt * 64) * 16;
            #pragma unroll
            for (int nb = 0; nb < 4; ++nb)
                #pragma unroll
                for (int e = 0; e < 4; ++e) acc1[nb][e] = 0.f;
            gemm_prol<6,2,16,32>(base32, tid, xh, xl, h1r_h, h1r_l, w1h, w1l, 48);
            gemm_main<6,2,16,32>(base32, tid, lane, wr, wc, xh, xl, h1r_h, h1r_l,
                                 w1h, w1l, 48, acc1);
        }
        if (do2) {
            #pragma unroll
            for (int nb = 0; nb < 4; ++nb)
                #pragma unroll
                for (int e = 0; e < 4; ++e) acc2[nb][e] = 0.f;
            gemm_prol<8,4,32,32>(base32, tid, h1r_h, h1r_l, h2r_h, h2r_l, w2h, w2l, 64);
        }
        if (do1) {
            const int wb = p & 1;
            uint2* dh = (uint2*)(g_h1_hi + ((size_t)wb * 512 + mt * 64) * 32 + jt * 2);
            uint2* dl = (uint2*)(g_h1_lo + ((size_t)wb * 512 + mt * 64) * 32 + jt * 2);
            epilogue(acc1, sG, s_b1, c1, dh, dl, (float*)0, tid, lane, wr, wc);
        }
        if (do2) {
            gemm_main<8,4,32,32>(base32, tid, lane, wr, wc, h1r_h, h1r_l, h2r_h, h2r_l,
                                 w2h, w2l, 64, acc2);
            const int wb = (p - 1) & 1;
            uint2* dh = (uint2*)(g_h2_hi + ((size_t)wb * 512 + mt * 64) * 32 + jt * 2);
            uint2* dl = (uint2*)(g_h2_lo + ((size_t)wb * 512 + mt * 64) * 32 + jt * 2);
            float* hb = (p == 1024) ? g_h2f + (size_t)(mt * 64) * 256 + jt * 16 : (float*)0;
            epilogue(acc2, sG, s_b2, c2, dh, dl, hb, tid, lane, wr, wc);
        }
        gbar(sense);                               // total 1026 barriers (even)
    }

    if (cta < 2) {
        int row = cta * 256 + tid;
        float s = 0.f;
        #pragma unroll 8
        for (int k = 0; k < H_; ++k) s += g_h2f[(size_t)row * H_ + k] * Wout[k];
        out[row] = s + bout[0];
    }
}

// ---------------- prep: split fp32 -> bf16 hi/lo planes ----------------
__global__ void prep_x_kernel(const float* __restrict__ x) {
    long gid = (long)blockIdx.x * 256 + threadIdx.x;
    int g = (int)(gid & 15);
    int b = (int)((gid >> 4) & 511);
    int t = (int)(gid >> 13);
    const float* src = x + ((size_t)b * 1024 + t) * 128 + g * 8;
    float4 f0 = *(const float4*)src, f1 = *(const float4*)(src + 4);
    float v[8] = {f0.x, f0.y, f0.z, f0.w, f1.x, f1.y, f1.z, f1.w};
    uint4 uh, ul;
    split8(v, uh, ul);
    size_t di = ((size_t)t * 512 + b) * 16 + g;
    g_x_hi[di] = uh; g_x_lo[di] = ul;
}

template<int K, int L>
__global__ void prep_w_kernel(const float* __restrict__ W) {
    uint4* dhi = (L == 1) ? g_w1_hi : g_w2_hi;
    uint4* dlo = (L == 1) ? g_w1_lo : g_w2_lo;
    int gid = blockIdx.x * 256 + threadIdx.x;
    int kg = gid % (K / 8);
    int np = gid / (K / 8);
    int jt = np >> 6, gate = (np >> 4) & 3, u = np & 15;
    int col = gate * 256 + jt * 16 + u;
    float v[8];
    #pragma unroll
    for (int e = 0; e < 8; ++e) v[e] = W[(size_t)(kg * 8 + e) * 1024 + col];
    uint4 uh, ul;
    split8(v, uh, ul);
    dhi[(size_t)np * (K / 8) + kg] = uh;
    dlo[(size_t)np * (K / 8) + kg] = ul;
}

extern "C" void kernel_launch(void* const* d_in, const int* in_sizes, int n_in,
                              void* d_out, int out_size)
{
    (void)in_sizes; (void)n_in; (void)out_size;
    const float* x    = (const float*)d_in[0];
    const float* W1   = (const float*)d_in[1];
    const float* b1   = (const float*)d_in[2];
    const float* W2   = (const float*)d_in[3];
    const float* b2   = (const float*)d_in[4];
    const float* Wout = (const float*)d_in[5];
    const float* bout = (const float*)d_in[6];
    cudaFuncSetAttribute(lstm_mma_kernel, cudaFuncAttributeMaxDynamicSharedMemorySize, SMEM_DYN);
    prep_x_kernel<<<32768, 256>>>(x);
    prep_w_kernel<384, 1><<<192, 256>>>(W1);
    prep_w_kernel<512, 2><<<256, 256>>>(W2);
    lstm_mma_kernel<<<NCTA, NTH, SMEM_DYN>>>(b1, b2, Wout, bout, (float*)d_out);
}